// round 1
// baseline (speedup 1.0000x reference)
#include <cuda_runtime.h>

#define T_LEN   4096
#define E_DIM   256
#define H_DIM   10
#define G_DIM   40          // 4*H
#define O_DIM   50257
#define HS_STR  16          // hs row stride (floats) -> 64B, sector-isolated rows
#define STRIPES 6
#define N_COLS  12565       // ceil(O/4)

__device__ float g_xg[T_LEN * G_DIM];     // precomputed input gate contributions
__device__ float g_hs[T_LEN * HS_STR];    // h_t, padded rows
__device__ int   g_progress;              // #timesteps published

// ---------------- helpers ----------------

__device__ __forceinline__ float sigf(float x) {
    // accurate-ish sigmoid: EX2-based expf (~1e-7 rel err) + approx div
    float e = __expf(-x);
    return __fdividef(1.0f, 1.0f + e);
}

__device__ __forceinline__ float tanh_acc(float x) {
    float e = __expf(-2.0f * x);
    return __fdividef(1.0f - e, 1.0f + e);
}

__device__ __forceinline__ int ld_acquire(const int* p) {
    int v;
    asm volatile("ld.global.acquire.gpu.b32 %0, [%1];" : "=r"(v) : "l"(p) : "memory");
    return v;
}

__device__ __forceinline__ void st_release(int* p, int v) {
    asm volatile("st.global.release.gpu.b32 [%0], %1;" :: "l"(p), "r"(v) : "memory");
}

// ---------------- kernel 1: embedding gather + xg precompute ----------------
// one warp per timestep; also resets the progress flag for this launch

__global__ void k_embed_gates(const int* __restrict__ x,
                              const float* __restrict__ emb,
                              const float* __restrict__ w_ih,
                              const float* __restrict__ b_ih,
                              const float* __restrict__ b_hh) {
    if (blockIdx.x == 0 && threadIdx.x == 0) g_progress = 0;

    int warp = blockIdx.x * (blockDim.x >> 5) + (threadIdx.x >> 5);
    int lane = threadIdx.x & 31;
    if (warp >= T_LEN) return;

    int tok = x[warp];
    const float* er = emb + (long)tok * E_DIM;
    float ev[8];
#pragma unroll
    for (int i = 0; i < 8; i++) ev[i] = er[lane + 32 * i];

    for (int r = 0; r < G_DIM; r++) {
        const float* wr = w_ih + r * E_DIM;
        float p = 0.f;
#pragma unroll
        for (int i = 0; i < 8; i++) p = fmaf(ev[i], wr[lane + 32 * i], p);
#pragma unroll
        for (int off = 16; off > 0; off >>= 1)
            p += __shfl_xor_sync(0xffffffffu, p, off);
        if (lane == 0)
            g_xg[warp * G_DIM + r] = p + b_ih[r] + b_hh[r];
    }
}

// ---------------- kernel 2: fused LSTM scan (producer) + logits GEMM (consumers) ----------------

__global__ __launch_bounds__(512, 1)
void k_lstm_logits(const float* __restrict__ w_hh,
                   const float* __restrict__ W_out,
                   const float* __restrict__ b_out,
                   float* __restrict__ out) {
    const int tid = threadIdx.x;
    const int bid = blockIdx.x;

    if (bid == 0 && tid < 32) {
        // =================== LSTM producer warp ===================
        const int lane = tid;
        const int kk = (lane < 10) ? lane : 0;   // clamp to avoid OOB weight reads

        float wI[10], wF[10], wG[10], wO[10];
#pragma unroll
        for (int j = 0; j < 10; j++) {
            wI[j] = w_hh[(0  + kk) * H_DIM + j];
            wF[j] = w_hh[(10 + kk) * H_DIM + j];
            wG[j] = w_hh[(20 + kk) * H_DIM + j];
            wO[j] = w_hh[(30 + kk) * H_DIM + j];
        }

        float c = 0.f;
        float hv[10];
#pragma unroll
        for (int j = 0; j < 10; j++) hv[j] = 0.f;

        // 2-deep prefetch of xg rows (L2-resident, ~234cyc)
        float a0 = g_xg[0 * G_DIM + 0  + kk];
        float a1 = g_xg[0 * G_DIM + 10 + kk];
        float a2 = g_xg[0 * G_DIM + 20 + kk];
        float a3 = g_xg[0 * G_DIM + 30 + kk];
        float b0 = g_xg[1 * G_DIM + 0  + kk];
        float b1 = g_xg[1 * G_DIM + 10 + kk];
        float b2 = g_xg[1 * G_DIM + 20 + kk];
        float b3 = g_xg[1 * G_DIM + 30 + kk];

        for (int t = 0; t < T_LEN; t++) {
            // prefetch t+2
            int tp = (t + 2 < T_LEN) ? (t + 2) : (T_LEN - 1);
            const float* xn = g_xg + tp * G_DIM;
            float n0 = xn[0  + kk];
            float n1 = xn[10 + kk];
            float n2 = xn[20 + kk];
            float n3 = xn[30 + kk];

            // dot products: split each into two 5-chains for shorter latency
            float siA = 0.f, siB = 0.f, sfA = 0.f, sfB = 0.f;
            float sgA = 0.f, sgB = 0.f, soA = 0.f, soB = 0.f;
#pragma unroll
            for (int j = 0; j < 5; j++) {
                siA = fmaf(hv[j],     wI[j],     siA);
                sfA = fmaf(hv[j],     wF[j],     sfA);
                sgA = fmaf(hv[j],     wG[j],     sgA);
                soA = fmaf(hv[j],     wO[j],     soA);
                siB = fmaf(hv[j + 5], wI[j + 5], siB);
                sfB = fmaf(hv[j + 5], wF[j + 5], sfB);
                sgB = fmaf(hv[j + 5], wG[j + 5], sgB);
                soB = fmaf(hv[j + 5], wO[j + 5], soB);
            }
            float gi = (siA + siB) + a0;
            float gf = (sfA + sfB) + a1;
            float gg = (sgA + sgB) + a2;
            float go = (soA + soB) + a3;

            float i_ = sigf(gi);
            float f_ = sigf(gf);
            float g_ = tanh_acc(gg);
            float o_ = sigf(go);

            c = fmaf(f_, c, i_ * g_);
            float hk = o_ * tanh_acc(c);

            // broadcast new h to all lanes
#pragma unroll
            for (int j = 0; j < 10; j++)
                hv[j] = __shfl_sync(0xffffffffu, hk, j);

            if (lane == 0) {
                float4* hrow = (float4*)(g_hs + t * HS_STR);
                hrow[0] = make_float4(hv[0], hv[1], hv[2], hv[3]);
                hrow[1] = make_float4(hv[4], hv[5], hv[6], hv[7]);
                *(float2*)(g_hs + t * HS_STR + 8) = make_float2(hv[8], hv[9]);
                st_release(&g_progress, t + 1);
            }

            a0 = b0; a1 = b1; a2 = b2; a3 = b3;
            b0 = n0; b1 = n1; b2 = n2; b3 = n3;
        }
        return;
    }

    // =================== GEMM consumers ===================
    // flat id over all non-producer threads; each owns 4 output columns and a t-stripe
    long gid = (long)bid * 512 + tid - 32;
    int col = (int)(gid % N_COLS);
    int s   = (int)(gid / N_COLS);
    if (s >= STRIPES) return;

    int o0 = col * 4;
    float w[4][10];
    float bb[4];
#pragma unroll
    for (int i = 0; i < 4; i++) {
        int o = o0 + i;
        if (o < O_DIM) {
            bb[i] = b_out[o];
#pragma unroll
            for (int k = 0; k < 10; k++) w[i][k] = W_out[o * H_DIM + k];
        } else {
            bb[i] = 0.f;
#pragma unroll
            for (int k = 0; k < 10; k++) w[i][k] = 0.f;
        }
    }

    int cur = 0;
    for (int t = s; t < T_LEN; t += STRIPES) {
        if (cur <= t) {
            do {
                cur = ld_acquire(&g_progress);
                if (cur <= t) __nanosleep((t - cur > 16) ? 1000u : 128u);
            } while (cur <= t);
        }

        float h[10];
#pragma unroll
        for (int k = 0; k < 10; k++) h[k] = g_hs[t * HS_STR + k];

        float acc0 = bb[0], acc1 = bb[1], acc2 = bb[2], acc3 = bb[3];
#pragma unroll
        for (int k = 0; k < 10; k++) {
            acc0 = fmaf(h[k], w[0][k], acc0);
            acc1 = fmaf(h[k], w[1][k], acc1);
            acc2 = fmaf(h[k], w[2][k], acc2);
            acc3 = fmaf(h[k], w[3][k], acc3);
        }

        float* dst = out + (long)t * O_DIM + o0;
        // scalar stores (row base alignment varies with t since O is odd)
        if (o0 + 3 < O_DIM) {
            dst[0] = acc0; dst[1] = acc1; dst[2] = acc2; dst[3] = acc3;
        } else {
            if (o0     < O_DIM) dst[0] = acc0;
            if (o0 + 1 < O_DIM) dst[1] = acc1;
            if (o0 + 2 < O_DIM) dst[2] = acc2;
            if (o0 + 3 < O_DIM) dst[3] = acc3;
        }
    }
}

// ---------------- launch ----------------

extern "C" void kernel_launch(void* const* d_in, const int* in_sizes, int n_in,
                              void* d_out, int out_size) {
    const int*   x    = (const int*)  d_in[0];
    const float* emb  = (const float*)d_in[1];
    const float* w_ih = (const float*)d_in[2];
    const float* w_hh = (const float*)d_in[3];
    const float* b_ih = (const float*)d_in[4];
    const float* b_hh = (const float*)d_in[5];
    const float* Wout = (const float*)d_in[6];
    const float* bout = (const float*)d_in[7];
    float* out = (float*)d_out;

    // kernel 1: 4096 warps (one per timestep), 8 warps/block
    k_embed_gates<<<T_LEN / 8, 256>>>(x, emb, w_ih, b_ih, b_hh);

    // kernel 2: exactly one wave (148 blocks x 512 threads, 1 block/SM guaranteed)
    k_lstm_logits<<<148, 512>>>(w_hh, Wout, bout, out);
}

// round 6
// speedup vs baseline: 1.1747x; 1.1747x over previous
#include <cuda_runtime.h>

#define T_LEN   4096
#define E_DIM   256
#define H_DIM   10
#define G_DIM   40
#define O_DIM   50257
#define HS_STR  16            // hs row stride (floats)
#define CHUNK   256
#define NCHUNK  (T_LEN / CHUNK)
#define COLS_PB 342           // 147 * 342 = 50274 >= O_DIM

// xg layout: [t][unit][gate] with gate in {0:i,1:f,2:g,3:o} -> float4 per unit
__device__ float g_xg[T_LEN * G_DIM];
__device__ float g_hs[T_LEN * HS_STR];
__device__ int   g_progress;          // # chunks published

// ---------------- helpers ----------------

__device__ __forceinline__ float sigf(float x) {
    float e = __expf(-x);
    return __frcp_rn(1.0f + e);
}

__device__ __forceinline__ float tanh_acc(float x) {
    float e = __expf(-2.0f * x);
    return __fdividef(1.0f - e, 1.0f + e);
}

__device__ __forceinline__ int ld_acquire(const int* p) {
    int v;
    asm volatile("ld.global.acquire.gpu.b32 %0, [%1];" : "=r"(v) : "l"(p) : "memory");
    return v;
}

__device__ __forceinline__ void st_release(int* p, int v) {
    asm volatile("st.global.release.gpu.b32 [%0], %1;" :: "l"(p), "r"(v) : "memory");
}

// ---------------- kernel 1: embedding gather + xg precompute ----------------

__global__ void k_embed_gates(const int* __restrict__ x,
                              const float* __restrict__ emb,
                              const float* __restrict__ w_ih,
                              const float* __restrict__ b_ih,
                              const float* __restrict__ b_hh) {
    if (blockIdx.x == 0 && threadIdx.x == 0) g_progress = 0;

    int warp = blockIdx.x * (blockDim.x >> 5) + (threadIdx.x >> 5);
    int lane = threadIdx.x & 31;
    if (warp >= T_LEN) return;

    int tok = x[warp];
    const float* er = emb + (long)tok * E_DIM;
    float ev[8];
#pragma unroll
    for (int i = 0; i < 8; i++) ev[i] = er[lane + 32 * i];

    for (int r = 0; r < G_DIM; r++) {
        const float* wr = w_ih + r * E_DIM;
        float p = 0.f;
#pragma unroll
        for (int i = 0; i < 8; i++) p = fmaf(ev[i], wr[lane + 32 * i], p);
#pragma unroll
        for (int off = 16; off > 0; off >>= 1)
            p += __shfl_xor_sync(0xffffffffu, p, off);
        if (lane == 0) {
            // transposed store: unit-major float4 {i,f,g,o}
            int unit = r % H_DIM;
            int gate = r / H_DIM;
            g_xg[warp * G_DIM + unit * 4 + gate] = p + b_ih[r] + b_hh[r];
        }
    }
}

// ---------------- kernel 2: LSTM producer (block 0) + chunked GEMM consumers ----------------

__global__ __launch_bounds__(512, 1)
void k_lstm_logits(const float* __restrict__ w_hh,
                   const float* __restrict__ W_out,
                   const float* __restrict__ b_out,
                   float* __restrict__ out) {
    const int tid = threadIdx.x;
    const int bid = blockIdx.x;

    if (bid == 0) {
        // =================== producer: single warp LSTM scan ===================
        if (tid >= 32) return;
        const int lane = tid;
        const int kk = (lane < H_DIM) ? lane : 0;

        float wI[10], wF[10], wG[10], wO[10];
#pragma unroll
        for (int j = 0; j < 10; j++) {
            wI[j] = w_hh[(0  + kk) * H_DIM + j];
            wF[j] = w_hh[(10 + kk) * H_DIM + j];
            wG[j] = w_hh[(20 + kk) * H_DIM + j];
            wO[j] = w_hh[(30 + kk) * H_DIM + j];
        }

        float c = 0.f;
        float hv[10];
#pragma unroll
        for (int j = 0; j < 10; j++) hv[j] = 0.f;

        // per-lane float4 xg stream, 2-deep prefetch
        const float4* xg4 = (const float4*)g_xg;   // [t*10 + unit]
        float4 xa = xg4[0 * H_DIM + kk];
        float4 xb = xg4[1 * H_DIM + kk];

        for (int t = 0; t < T_LEN; t++) {
            int tp = (t + 2 < T_LEN) ? (t + 2) : (T_LEN - 1);
            float4 xn = xg4[tp * H_DIM + kk];

            float siA = 0.f, siB = 0.f, sfA = 0.f, sfB = 0.f;
            float sgA = 0.f, sgB = 0.f, soA = 0.f, soB = 0.f;
#pragma unroll
            for (int j = 0; j < 5; j++) {
                siA = fmaf(hv[j],     wI[j],     siA);
                sfA = fmaf(hv[j],     wF[j],     sfA);
                sgA = fmaf(hv[j],     wG[j],     sgA);
                soA = fmaf(hv[j],     wO[j],     soA);
                siB = fmaf(hv[j + 5], wI[j + 5], siB);
                sfB = fmaf(hv[j + 5], wF[j + 5], sfB);
                sgB = fmaf(hv[j + 5], wG[j + 5], sgB);
                soB = fmaf(hv[j + 5], wO[j + 5], soB);
            }
            float gi = (siA + siB) + xa.x;
            float gf = (sfA + sfB) + xa.y;
            float gg = (sgA + sgB) + xa.z;
            float go = (soA + soB) + xa.w;

            float i_ = sigf(gi);
            float f_ = sigf(gf);
            float g_ = tanh_acc(gg);
            float o_ = sigf(go);

            c = fmaf(f_, c, i_ * g_);
            float hk = o_ * tanh_acc(c);

            // per-lane h store (plain); ordered at chunk boundary below
            if (lane < H_DIM)
                g_hs[t * HS_STR + lane] = hk;

            // broadcast new h to all lanes for the next step's dots
#pragma unroll
            for (int j = 0; j < 10; j++)
                hv[j] = __shfl_sync(0xffffffffu, hk, j);

            // publish once per chunk
            if ((t & (CHUNK - 1)) == (CHUNK - 1)) {
                __syncwarp();                     // order all lanes' g_hs stores
                if (lane == 0) {
                    __threadfence();              // cumulative gpu-scope fence
                    st_release(&g_progress, (t >> 8) + 1);
                }
            }

            xa = xb;
            xb = xn;
        }
        return;
    }

    // =================== consumers: chunk-synchronous GEMM ===================
    __shared__ float sh[CHUNK * H_DIM];   // 10 KB h-chunk stage
    __shared__ int   s_ready;

    const int col = (bid - 1) * COLS_PB + tid;       // tid < COLS_PB owns a column
    const bool active = (tid < COLS_PB) && (col < O_DIM);

    float w[10];
    float bias = 0.f;
    if (active) {
        bias = b_out[col];
#pragma unroll
        for (int k = 0; k < 10; k++) w[k] = W_out[col * H_DIM + k];
    }

    for (int q = 0; q < NCHUNK; q++) {
        // one poller per block
        if (tid == 0) {
            int cur = ld_acquire(&g_progress);
            while (cur <= q) {
                __nanosleep(256);
                cur = ld_acquire(&g_progress);
            }
            s_ready = cur;
        }
        __syncthreads();

        // cooperative stage of this chunk's h rows into smem
        const int tbase = q * CHUNK;
        for (int i = tid; i < CHUNK * H_DIM; i += 512) {
            int t = i / H_DIM, k = i - t * H_DIM;
            sh[i] = g_hs[(tbase + t) * HS_STR + k];
        }
        __syncthreads();

        if (active) {
            float* dst = out + (long)tbase * O_DIM + col;
#pragma unroll 1
            for (int t = 0; t < CHUNK; t += 4) {
                const float* h0 = sh + (t + 0) * H_DIM;
                const float* h1 = sh + (t + 1) * H_DIM;
                const float* h2 = sh + (t + 2) * H_DIM;
                const float* h3 = sh + (t + 3) * H_DIM;
                float acc0 = bias, acc1 = bias, acc2 = bias, acc3 = bias;
#pragma unroll
                for (int k = 0; k < 10; k++) {
                    acc0 = fmaf(h0[k], w[k], acc0);
                    acc1 = fmaf(h1[k], w[k], acc1);
                    acc2 = fmaf(h2[k], w[k], acc2);
                    acc3 = fmaf(h3[k], w[k], acc3);
                }
                dst[(long)(t + 0) * O_DIM] = acc0;
                dst[(long)(t + 1) * O_DIM] = acc1;
                dst[(long)(t + 2) * O_DIM] = acc2;
                dst[(long)(t + 3) * O_DIM] = acc3;
            }
        }
        __syncthreads();   // protect smem reuse next chunk
    }
}

// ---------------- launch ----------------

extern "C" void kernel_launch(void* const* d_in, const int* in_sizes, int n_in,
                              void* d_out, int out_size) {
    const int*   x    = (const int*)  d_in[0];
    const float* emb  = (const float*)d_in[1];
    const float* w_ih = (const float*)d_in[2];
    const float* w_hh = (const float*)d_in[3];
    const float* b_ih = (const float*)d_in[4];
    const float* b_hh = (const float*)d_in[5];
    const float* Wout = (const float*)d_in[6];
    const float* bout = (const float*)d_in[7];
    float* out = (float*)d_out;

    k_embed_gates<<<T_LEN / 8, 256>>>(x, emb, w_ih, b_ih, b_hh);
    k_lstm_logits<<<148, 512>>>(w_hh, Wout, bout, out);
}

// round 13
// speedup vs baseline: 3.0732x; 2.6160x over previous
#include <cuda_runtime.h>

#define T_LEN   4096
#define E_DIM   256
#define H_DIM   10
#define G_DIM   40
#define O_DIM   50257
#define HS_STR  16            // hs row stride (floats)
#define CHUNK   256
#define NCHUNK  (T_LEN / CHUNK)
#define COLS_PB 342           // 147 * 342 = 50274 >= O_DIM
#define NBLK    148

#define LOG2E_F 1.4426950408889634f

// xg layout: [t][unit][gate], gate in {0:i,1:f,2:g,3:o} -> one float4 per unit
__device__ float g_xg[T_LEN * G_DIM];
__device__ float g_hs[T_LEN * HS_STR];
__device__ int   g_pmir[NBLK * 32];   // per-block progress mirror, one 128B line each

// ---------------- helpers ----------------

__device__ __forceinline__ float ex2f(float x) {
    float r;
    asm("ex2.approx.f32 %0, %1;" : "=f"(r) : "f"(x));
    return r;
}

__device__ __forceinline__ float rcpf(float x) {
    float r;
    asm("rcp.approx.f32 %0, %1;" : "=f"(r) : "f"(x));
    return r;
}

__device__ __forceinline__ int ld_acquire(const int* p) {
    int v;
    asm volatile("ld.global.acquire.gpu.b32 %0, [%1];" : "=r"(v) : "l"(p) : "memory");
    return v;
}

__device__ __forceinline__ void st_release(int* p, int v) {
    asm volatile("st.global.release.gpu.b32 [%0], %1;" :: "l"(p), "r"(v) : "memory");
}

// ---------------- kernel 1: embedding gather + xg precompute ----------------

__global__ void k_embed_gates(const int* __restrict__ x,
                              const float* __restrict__ emb,
                              const float* __restrict__ w_ih,
                              const float* __restrict__ b_ih,
                              const float* __restrict__ b_hh) {
    if (blockIdx.x == 0 && threadIdx.x < NBLK)
        g_pmir[threadIdx.x * 32] = 0;        // reset flags for this launch

    int warp = blockIdx.x * (blockDim.x >> 5) + (threadIdx.x >> 5);
    int lane = threadIdx.x & 31;
    if (warp >= T_LEN) return;

    int tok = x[warp];
    const float* er = emb + (long)tok * E_DIM;
    float ev[8];
#pragma unroll
    for (int i = 0; i < 8; i++) ev[i] = er[lane + 32 * i];

    for (int r = 0; r < G_DIM; r++) {
        const float* wr = w_ih + r * E_DIM;
        float p = 0.f;
#pragma unroll
        for (int i = 0; i < 8; i++) p = fmaf(ev[i], wr[lane + 32 * i], p);
#pragma unroll
        for (int off = 16; off > 0; off >>= 1)
            p += __shfl_xor_sync(0xffffffffu, p, off);
        if (lane == 0) {
            int unit = r % H_DIM;
            int gate = r / H_DIM;
            g_xg[warp * G_DIM + unit * 4 + gate] = p + b_ih[r] + b_hh[r];
        }
    }
}

// ---------------- kernel 2: LSTM producer (block 0) + spinning GEMM consumers ----------------
// sigmoid(x) = RCP(1 + EX2(-x*log2e))
// tanh(x)    = fma(2, RCP(1 + EX2(-2x*log2e)), -1)

#define LSTM_STEP(XA, TT)                                                     \
{                                                                             \
    float siA=0.f,siB=0.f,sfA=0.f,sfB=0.f,sgA=0.f,sgB=0.f,soA=0.f,soB=0.f;    \
    _Pragma("unroll")                                                         \
    for (int j = 0; j < 5; j++) {                                             \
        siA = fmaf(hv[j],     wI[j],     siA);                                \
        sfA = fmaf(hv[j],     wF[j],     sfA);                                \
        sgA = fmaf(hv[j],     wG[j],     sgA);                                \
        soA = fmaf(hv[j],     wO[j],     soA);                                \
        siB = fmaf(hv[j + 5], wI[j + 5], siB);                                \
        sfB = fmaf(hv[j + 5], wF[j + 5], sfB);                                \
        sgB = fmaf(hv[j + 5], wG[j + 5], sgB);                                \
        soB = fmaf(hv[j + 5], wO[j + 5], soB);                                \
    }                                                                         \
    float gi = (siA + siB) + (XA).x;                                          \
    float gf = (sfA + sfB) + (XA).y;                                          \
    float gg = (sgA + sgB) + (XA).z;                                          \
    float go = (soA + soB) + (XA).w;                                          \
    float ei = ex2f(gi * (-LOG2E_F));                                         \
    float ef = ex2f(gf * (-LOG2E_F));                                         \
    float eg = ex2f(gg * (-2.0f * LOG2E_F));                                  \
    float eo = ex2f(go * (-LOG2E_F));                                         \
    float i_ = rcpf(1.0f + ei);                                               \
    float f_ = rcpf(1.0f + ef);                                               \
    float o_ = rcpf(1.0f + eo);                                               \
    float g_ = fmaf(2.0f, rcpf(1.0f + eg), -1.0f);                            \
    c = fmaf(f_, c, i_ * g_);                                                 \
    float ec = ex2f(c * (-2.0f * LOG2E_F));                                   \
    float th = fmaf(2.0f, rcpf(1.0f + ec), -1.0f);                            \
    float hk = o_ * th;                                                       \
    if (lane < H_DIM) g_hs[(TT) * HS_STR + lane] = hk;                        \
    _Pragma("unroll")                                                         \
    for (int j = 0; j < 10; j++) hv[j] = __shfl_sync(0xffffffffu, hk, j);     \
}

__global__ __launch_bounds__(512, 1)
void k_lstm_logits(const float* __restrict__ w_hh,
                   const float* __restrict__ W_out,
                   const float* __restrict__ b_out,
                   float* __restrict__ out) {
    const int tid = threadIdx.x;
    const int bid = blockIdx.x;

    if (bid == 0) {
        // =================== producer: single-warp LSTM scan ===================
        if (tid >= 32) return;
        const int lane = tid;
        const int kk = (lane < H_DIM) ? lane : 0;

        float wI[10], wF[10], wG[10], wO[10];
#pragma unroll
        for (int j = 0; j < 10; j++) {
            wI[j] = w_hh[(0  + kk) * H_DIM + j];
            wF[j] = w_hh[(10 + kk) * H_DIM + j];
            wG[j] = w_hh[(20 + kk) * H_DIM + j];
            wO[j] = w_hh[(30 + kk) * H_DIM + j];
        }

        float c = 0.f;
        float hv[10];
#pragma unroll
        for (int j = 0; j < 10; j++) hv[j] = 0.f;

        const float4* xg4 = (const float4*)g_xg;   // [t*10 + unit]
        float4 p0 = xg4[0 * H_DIM + kk];
        float4 p1 = xg4[1 * H_DIM + kk];
        float4 p2 = xg4[2 * H_DIM + kk];
        float4 p3 = xg4[3 * H_DIM + kk];

        for (int t = 0; t < T_LEN; t += 4) {
            // prefetch next group of 4 (distance 4..7, clamped at tail)
            int c0 = (t + 4 < T_LEN) ? t + 4 : T_LEN - 1;
            int c1 = (t + 5 < T_LEN) ? t + 5 : T_LEN - 1;
            int c2 = (t + 6 < T_LEN) ? t + 6 : T_LEN - 1;
            int c3 = (t + 7 < T_LEN) ? t + 7 : T_LEN - 1;
            float4 n0 = xg4[c0 * H_DIM + kk];
            float4 n1 = xg4[c1 * H_DIM + kk];
            float4 n2 = xg4[c2 * H_DIM + kk];
            float4 n3 = xg4[c3 * H_DIM + kk];

            LSTM_STEP(p0, t + 0);
            LSTM_STEP(p1, t + 1);
            LSTM_STEP(p2, t + 2);
            LSTM_STEP(p3, t + 3);

            // chunk boundary at t+3 (CHUNK divisible by 4)
            if ((t & (CHUNK - 1)) == CHUNK - 4) {
                __syncwarp();          // order all lanes' g_hs stores
                __threadfence();       // publish at gpu scope
                int q1 = (t >> 8) + 1;
#pragma unroll
                for (int m = lane; m < NBLK; m += 32)
                    st_release(&g_pmir[m * 32], q1);
            }

            p0 = n0; p1 = n1; p2 = n2; p3 = n3;
        }
        return;
    }

    // =================== consumers: spin-wait + chunked GEMM ===================
    __shared__ float sh[CHUNK * H_DIM];   // 10 KB h-chunk stage

    const int* my_flag = &g_pmir[bid * 32];
    const int col = (bid - 1) * COLS_PB + tid;
    const bool active = (tid < COLS_PB) && (col < O_DIM);

    float w[10];
    float bias = 0.f;
    if (active) {
        bias = b_out[col];
#pragma unroll
        for (int k = 0; k < 10; k++) w[k] = W_out[col * H_DIM + k];
    }

    for (int q = 0; q < NCHUNK; q++) {
        // ALL threads busy-spin (keeps SMs active -> clocks boost); per-block flag line
        while (ld_acquire(my_flag) <= q) { }
        __syncthreads();

        // cooperative stage of this chunk's h rows into smem
        const int tbase = q * CHUNK;
        for (int i = tid; i < CHUNK * H_DIM; i += 512) {
            int t = i / H_DIM, k = i - t * H_DIM;
            sh[i] = g_hs[(tbase + t) * HS_STR + k];
        }
        __syncthreads();

        if (active) {
            float* dst = out + (long)tbase * O_DIM + col;
#pragma unroll 1
            for (int t = 0; t < CHUNK; t += 4) {
                const float* h0 = sh + (t + 0) * H_DIM;
                const float* h1 = sh + (t + 1) * H_DIM;
                const float* h2 = sh + (t + 2) * H_DIM;
                const float* h3 = sh + (t + 3) * H_DIM;
                float acc0 = bias, acc1 = bias, acc2 = bias, acc3 = bias;
#pragma unroll
                for (int k = 0; k < 10; k++) {
                    acc0 = fmaf(h0[k], w[k], acc0);
                    acc1 = fmaf(h1[k], w[k], acc1);
                    acc2 = fmaf(h2[k], w[k], acc2);
                    acc3 = fmaf(h3[k], w[k], acc3);
                }
                dst[(long)(t + 0) * O_DIM] = acc0;
                dst[(long)(t + 1) * O_DIM] = acc1;
                dst[(long)(t + 2) * O_DIM] = acc2;
                dst[(long)(t + 3) * O_DIM] = acc3;
            }
        }
        __syncthreads();   // protect smem reuse next chunk
    }
}

// ---------------- launch ----------------

extern "C" void kernel_launch(void* const* d_in, const int* in_sizes, int n_in,
                              void* d_out, int out_size) {
    const int*   x    = (const int*)  d_in[0];
    const float* emb  = (const float*)d_in[1];
    const float* w_ih = (const float*)d_in[2];
    const float* w_hh = (const float*)d_in[3];
    const float* b_ih = (const float*)d_in[4];
    const float* b_hh = (const float*)d_in[5];
    const float* Wout = (const float*)d_in[6];
    const float* bout = (const float*)d_in[7];
    float* out = (float*)d_out;

    k_embed_gates<<<T_LEN / 8, 256>>>(x, emb, w_ih, b_ih, b_hh);
    k_lstm_logits<<<NBLK, 512>>>(w_hh, Wout, bout, out);
}